// round 9
// baseline (speedup 1.0000x reference)
#include <cuda_runtime.h>
#include <math.h>

// CurveGraphic2d: 16 cubic Beziers -> 16 x 256x256 canvases.
// canvas = clip(1 - (min_d/w + eps)^aa, 0, 1); w <= 8 so min_d >= w gives
// exactly 0 -> zero-fill everything, then render ONLY the active tiles from
// a compacted worklist (no blocks launched-and-stalled for dead tiles).

#define CANVAS_H 256
#define CANVAS_W 256
#define NSAMP 32
#define MAX_LEN 300.0f
#define EPS 1e-6f

__device__ float2         g_samples[16][NSAMP];   // (y, x) per sample
__device__ unsigned short g_worklist[16 * 256];   // per-curve segments of active tiles
__device__ int            g_countb[16];           // active tiles per curve

// ---------------- Kernel 1: zero-fill output (grid=1024) --------------------
__global__ __launch_bounds__(256)
void zero_fill_kernel(float4* __restrict__ out, int n4)
{
    const int i = blockIdx.x * 256 + threadIdx.x;
    if (i < n4) out[i] = make_float4(0.f, 0.f, 0.f, 0.f);
}

// ---------------- Kernel 2: samples + tile cull + compaction (grid=16) ------
__global__ __launch_bounds__(256)
void curve_setup_kernel(const float* __restrict__ inputs,   // [16,4,2]
                        const float* __restrict__ widths)   // [16]
{
    __shared__ float4 ssamp[NSAMP / 2];
    __shared__ int s_cnt;

    const int b   = blockIdx.x;
    const int tid = threadIdx.x;

    if (tid == 0) s_cnt = 0;

    if (tid < 32) {
        const int s = tid;
        float cy[4], cx[4];
#pragma unroll
        for (int i = 0; i < 4; i++) {
            cy[i] = inputs[(b * 4 + i) * 2 + 0] * (float)CANVAS_H;
            cx[i] = inputs[(b * 4 + i) * 2 + 1] * (float)CANVAS_W;
        }

        const float t = (float)s / 31.0f;           // linspace(0,1,32)
        const float u = 1.0f - t;
        const float B0 = u * u * u;
        const float B1 = 3.0f * t * u * u;
        const float B2 = 3.0f * t * t * u;
        const float B3 = t * t * t;

        // Full-curve sample (arc length)
        const float py = B0 * cy[0] + B1 * cy[1] + B2 * cy[2] + B3 * cy[3];
        const float px = B0 * cx[0] + B1 * cx[1] + B2 * cx[2] + B3 * cx[3];

        const float pym = __shfl_up_sync(0xffffffffu, py, 1);
        const float pxm = __shfl_up_sync(0xffffffffu, px, 1);
        const float dyy = py - pym;
        const float dxx = px - pxm;
        float seg = (s > 0) ? sqrtf(dyy * dyy + dxx * dxx) : 0.0f;
#pragma unroll
        for (int off = 16; off; off >>= 1)
            seg += __shfl_xor_sync(0xffffffffu, seg, off);
        const float arc = seg;

        const float tt = fminf(1.0f, MAX_LEN / (arc + EPS));
        const float ut = 1.0f - tt;

        // de Casteljau left subdivision at tt
        const float b0y = ut * cy[0] + tt * cy[1], b0x = ut * cx[0] + tt * cx[1];
        const float b1y = ut * cy[1] + tt * cy[2], b1x = ut * cx[1] + tt * cx[2];
        const float b2y = ut * cy[2] + tt * cy[3], b2x = ut * cx[2] + tt * cx[3];
        const float c0y = ut * b0y + tt * b1y,     c0x = ut * b0x + tt * b1x;
        const float c1y = ut * b1y + tt * b2y,     c1x = ut * b1x + tt * b2x;
        const float d0y = ut * c0y + tt * c1y,     d0x = ut * c0x + tt * c1x;

        // Truncated-curve sample
        const float sy = B0 * cy[0] + B1 * b0y + B2 * c0y + B3 * d0y;
        const float sx = B0 * cx[0] + B1 * b0x + B2 * c0x + B3 * d0x;

        ((float2*)ssamp)[s] = make_float2(sy, sx);
        g_samples[b][s]     = make_float2(sy, sx);
    }
    __syncthreads();

    // Each thread culls one 16x16 tile of canvas b; active tiles are compacted.
    const int tile = tid;
    const float tcy = (float)((tile >> 4) << 4) + 7.5f;
    const float tcx = (float)((tile & 15) << 4) + 7.5f;
    float m = 3.4e38f;
#pragma unroll
    for (int k = 0; k < NSAMP / 2; k++) {
        const float4 v = ssamp[k];
        const float dy0 = tcy - v.x;
        const float dx0 = tcx - v.y;
        m = fminf(m, fmaf(dy0, dy0, dx0 * dx0));
        const float dy1 = tcy - v.z;
        const float dx1 = tcx - v.w;
        m = fminf(m, fmaf(dy1, dy1, dx1 * dx1));
    }
    // Tile half-diagonal 8*sqrt(2)=11.3137 + 1 px fp-safety margin.
    const float thr = widths[b] + 11.3137085f + 1.0f;
    if (m < thr * thr) {
        const int p = atomicAdd(&s_cnt, 1);        // order irrelevant: tiles disjoint
        g_worklist[(b << 8) + p] = (unsigned short)tile;
    }
    __syncthreads();
    if (tid == 0) g_countb[b] = s_cnt;
}

// ---------------- Kernel 3: render active tiles only (grid=1024) ------------
__global__ __launch_bounds__(256)
void curve_render_kernel(const float* __restrict__ widths,  // [16]
                         const float* __restrict__ aafac,   // [16]
                         float* __restrict__ out)           // [16,256,256]
{
    __shared__ int s_cnt[16];

    const int tid = threadIdx.x;
    if (tid < 16) s_cnt[tid] = g_countb[tid];
    __syncthreads();

    int total = 0;
#pragma unroll
    for (int i = 0; i < 16; i++) total += s_cnt[i];

    for (int item = blockIdx.x; item < total; item += gridDim.x) {
        // Map global work index -> (curve b, local index g)
        int g = item, b = 0;
        while (g >= s_cnt[b]) { g -= s_cnt[b]; b++; }
        const int tile = (int)g_worklist[(b << 8) + g];
        const int ty0  = (tile >> 4) << 4;
        const int tx0  = (tile & 15) << 4;

        const int lx = tid & 15;
        const int ly = tid >> 4;
        const int py = ty0 + ly;
        const int px = tx0 + lx;

        const float w = __ldg(&widths[b]);

        // Warp cull: each warp covers a 2x16 strip; background already zero.
        {
            const int lane = tid & 31;
            const float2 sp = __ldg(&g_samples[b][lane]);
            const float wcy = (float)(ty0 + (ly & ~1)) + 0.5f;
            const float wcx = (float)tx0 + 7.5f;
            const float ddy = wcy - sp.x;
            const float ddx = wcx - sp.y;
            float d2 = ddy * ddy + ddx * ddx;
#pragma unroll
            for (int off = 16; off; off >>= 1)
                d2 = fminf(d2, __shfl_xor_sync(0xffffffffu, d2, off));
            // Strip half-diagonal sqrt(7.5^2+0.5^2)=7.5166 + 0.5 margin.
            const float thr = w + 7.517f + 0.5f;
            if (d2 >= thr * thr) continue;            // warp-uniform
        }

        // Full evaluation: min squared distance over 32 samples.
        const float4* __restrict__ gs = (const float4*)g_samples[b];
        const float fy = (float)py;
        const float fx = (float)px;
        float m = 3.4e38f;
#pragma unroll
        for (int k = 0; k < NSAMP / 2; k++) {
            const float4 v = __ldg(&gs[k]);           // uniform LDG.128 broadcast
            const float dy0 = fy - v.x;
            const float dx0 = fx - v.y;
            m = fminf(m, fmaf(dy0, dy0, dx0 * dx0));
            const float dy1 = fy - v.z;
            const float dx1 = fx - v.w;
            m = fminf(m, fmaf(dy1, dy1, dx1 * dx1));
        }

        const float md   = sqrtf(m);
        const float base = md / w + EPS;
        const float val  = 1.0f - __powf(base, __ldg(&aafac[b]));
        out[(((b << 8) + py) << 8) + px] = fminf(fmaxf(val, 0.0f), 1.0f);
    }
}

extern "C" void kernel_launch(void* const* d_in, const int* in_sizes, int n_in,
                              void* d_out, int out_size)
{
    const float* inputs = (const float*)d_in[0];   // [16,4,2]
    const float* widths = (const float*)d_in[1];   // [16]
    const float* aafac  = (const float*)d_in[2];   // [16]
    float* out = (float*)d_out;                    // [16,256,256]

    const int n4 = out_size / 4;                   // 262144 float4s
    zero_fill_kernel<<<(n4 + 255) / 256, 256>>>((float4*)out, n4);
    curve_setup_kernel<<<16, 256>>>(inputs, widths);
    curve_render_kernel<<<1024, 256>>>(widths, aafac, out);
}